// round 14
// baseline (speedup 1.0000x reference)
#include <cuda_runtime.h>
#include <cuda_bf16.h>
#include <cuda_fp16.h>
#include <math.h>
#include <cstdint>
#include <cstddef>

#define NN 2048
#define CN 256
#define XP 4224          // padded column stride (33*128)
#define FBC 4160         // real columns = 65*64
#define SSTRIDE 131072   // NN*64
#define ELLW 128
#define KP 80            // padded f-dim for node mma W tiles (bf16, 160B rows)

// ---------------- scratch (device globals) ---------------------------------
__device__ __nv_bfloat16 g_x0h[(size_t)NN * XP];
__device__ __nv_bfloat16 g_x0l[(size_t)NN * XP];
__device__ __half        g_x0fA[(size_t)NN * XP];
__device__ __half        g_x0fB[(size_t)NN * XP];
__device__ __nv_bfloat16 g_fch[(size_t)CN * XP];
__device__ __nv_bfloat16 g_fcl[(size_t)CN * XP];
__device__ __nv_bfloat16 g_afch[(size_t)CN * NN];
__device__ __nv_bfloat16 g_afcl[(size_t)CN * NN];
__device__ __nv_bfloat16 g_afcth[(size_t)NN * CN];
__device__ __nv_bfloat16 g_afctl[(size_t)NN * CN];
__device__ __nv_bfloat16 g_wt0h[128 * KP];   // W0^T [j][f] hi, zero-padded f>=65
__device__ __nv_bfloat16 g_wt0l[128 * KP];
__device__ __nv_bfloat16 g_wt1h[64 * KP];
__device__ __nv_bfloat16 g_wt1l[64 * KP];
__device__ float    g_x1[(size_t)NN * XP];
__device__ float    g_u[(size_t)64 * SSTRIDE];
__device__ unsigned short g_cols[(size_t)NN * ELLW];
__device__ float    g_wts[(size_t)NN * ELLW];
__device__ int      g_nnz[NN];

__device__ __forceinline__ float sigf(float x) { return 1.0f / (1.0f + expf(-x)); }
__device__ __forceinline__ void splitf(float v, __nv_bfloat16& h, __nv_bfloat16& l) {
    h = __float2bfloat16(v);
    l = __float2bfloat16(v - __bfloat162float(h));
}
__device__ __forceinline__ uint32_t smem_u32(const void* p) {
    uint32_t a;
    asm("{ .reg .u64 t; cvta.to.shared.u64 t, %1; cvt.u32.u64 %0, t; }" : "=r"(a) : "l"(p));
    return a;
}
__device__ __forceinline__ void cpasync16(uint32_t s, const void* g) {
    asm volatile("cp.async.cg.shared.global [%0], [%1], 16;" :: "r"(s), "l"(g));
}
#define CP_COMMIT() asm volatile("cp.async.commit_group;" ::: "memory")
template<int N> __device__ __forceinline__ void cp_wait() {
    asm volatile("cp.async.wait_group %0;" :: "n"(N) : "memory");
}
__device__ __forceinline__ void sts128u(uint32_t a, uint4 v) {
    asm volatile("st.shared.v4.b32 [%0], {%1,%2,%3,%4};"
        :: "r"(a), "r"(v.x), "r"(v.y), "r"(v.z), "r"(v.w));
}
__device__ __forceinline__ void ldsm4(uint32_t* r, uint32_t a) {
    asm volatile("ldmatrix.sync.aligned.m8n8.x4.shared.b16 {%0,%1,%2,%3}, [%4];"
        : "=r"(r[0]), "=r"(r[1]), "=r"(r[2]), "=r"(r[3]) : "r"(a));
}
__device__ __forceinline__ void ldsm4t(uint32_t* r, uint32_t a) {
    asm volatile("ldmatrix.sync.aligned.m8n8.x4.trans.shared.b16 {%0,%1,%2,%3}, [%4];"
        : "=r"(r[0]), "=r"(r[1]), "=r"(r[2]), "=r"(r[3]) : "r"(a));
}
__device__ __forceinline__ void mma_bf16(float* c, const uint32_t* a, uint32_t b0, uint32_t b1) {
    asm volatile("mma.sync.aligned.m16n8k16.row.col.f32.bf16.bf16.f32 "
        "{%0,%1,%2,%3}, {%4,%5,%6,%7}, {%8,%9}, {%0,%1,%2,%3};"
        : "+f"(c[0]), "+f"(c[1]), "+f"(c[2]), "+f"(c[3])
        : "r"(a[0]), "r"(a[1]), "r"(a[2]), "r"(a[3]), "r"(b0), "r"(b1));
}

// ---------------------------------------------------------------------------
// setup: ELL compaction + weight converts + pack x0 (blocks 0/1 also do W^T)
// ---------------------------------------------------------------------------
__global__ __launch_bounds__(256) void setup_kernel(const float* __restrict__ adj,
    const float* __restrict__ afc, const float* __restrict__ afct,
    const float* __restrict__ inputs, const float* __restrict__ state,
    const float* __restrict__ w0, const float* __restrict__ w1)
{
    __shared__ float tile[64 * 65];
    __shared__ int wsum[8];
    const int n = blockIdx.x, t = threadIdx.x;
    const int lane = t & 31, wid = t >> 5;

    {
        int i = n * 256 + t;
        __nv_bfloat16 h, l;
        splitf(afc[i],  h, l); g_afch[i]  = h; g_afcl[i]  = l;
        splitf(afct[i], h, l); g_afcth[i] = h; g_afctl[i] = l;
    }
    if (n == 0) {
        for (int idx = t; idx < 128 * KP; idx += 256) {
            int j = idx / KP, f = idx % KP;
            float v = (f < 65) ? w0[f * 128 + j] : 0.f;
            __nv_bfloat16 h, l; splitf(v, h, l);
            g_wt0h[idx] = h; g_wt0l[idx] = l;
        }
    }
    if (n == 1) {
        for (int idx = t; idx < 64 * KP; idx += 256) {
            int j = idx / KP, f = idx % KP;
            float v = (f < 65) ? w1[f * 64 + j] : 0.f;
            __nv_bfloat16 h, l; splitf(v, h, l);
            g_wt1h[idx] = h; g_wt1l[idx] = l;
        }
    }

    const float* row = adj + (size_t)n * NN;
    float v[8];
    float4 p0 = *(const float4*)(row + t * 8);
    float4 p1 = *(const float4*)(row + t * 8 + 4);
    v[0] = p0.x; v[1] = p0.y; v[2] = p0.z; v[3] = p0.w;
    v[4] = p1.x; v[5] = p1.y; v[6] = p1.z; v[7] = p1.w;
    int cnt = 0;
#pragma unroll
    for (int q = 0; q < 8; q++) cnt += (v[q] != 0.0f);
    int inc = cnt;
#pragma unroll
    for (int off = 1; off < 32; off <<= 1) {
        int y = __shfl_up_sync(0xFFFFFFFFu, inc, off);
        if (lane >= off) inc += y;
    }
    if (lane == 31) wsum[wid] = inc;
    __syncthreads();
    int wbase = 0;
#pragma unroll
    for (int w = 0; w < 8; w++) wbase += (w < wid) ? wsum[w] : 0;
    int pos = wbase + inc - cnt;
#pragma unroll
    for (int q = 0; q < 8; q++) {
        if (v[q] != 0.0f) {
            if (pos < ELLW) {
                g_cols[(size_t)n * ELLW + pos] = (unsigned short)(t * 8 + q);
                g_wts[(size_t)n * ELLW + pos] = v[q];
            }
            pos++;
        }
    }
    if (t == 255) g_nnz[n] = (pos < ELLW) ? pos : ELLW;

    for (int i = t; i < 4096; i += 256) {
        int b = i >> 6, u = i & 63;
        tile[b * 65 + u] = state[(size_t)b * SSTRIDE + n * 64 + u];
    }
    __syncthreads();
    __nv_bfloat16* rh = g_x0h + (size_t)n * XP;
    __nv_bfloat16* rl = g_x0l + (size_t)n * XP;
    __half*        rf = g_x0fA + (size_t)n * XP;
    if (t < 64) {
        float vv = inputs[t * NN + n];
        __nv_bfloat16 h, l; splitf(vv, h, l);
        rh[t] = h; rl[t] = l; rf[t] = __float2half(vv);
    }
    for (int i = t; i < 4096; i += 256) {
        int u = i >> 6, b = i & 63;
        float vv = tile[b * 65 + u];
        __nv_bfloat16 h, l; splitf(vv, h, l);
        rh[64 + i] = h; rl[64 + i] = l; rf[64 + i] = __float2half(vv);
    }
}

// ---------------------------------------------------------------------------
// dense gemm (R10 config): C(Mx4224) = A(MxK) @ B(Kx4224)
// ---------------------------------------------------------------------------
template<int BM, int EPI, int NS>
__global__ __launch_bounds__(256, 2) void gemm_mma(
    const __nv_bfloat16* __restrict__ Ah, const __nv_bfloat16* __restrict__ Al,
    const __nv_bfloat16* __restrict__ Bh, const __nv_bfloat16* __restrict__ Bl,
    void* __restrict__ C0, void* __restrict__ C1, int K, int lda, int ldb)
{
    extern __shared__ char smem[];
    constexpr int ABYTES = BM * 128;
    constexpr int STAGE  = ABYTES + 16384;
    constexpr int WARPS_M = BM / 32;
    constexpr int WNT = 128 / (8 / WARPS_M);
    constexpr int NB = WNT / 8, NG = WNT / 16;

    const uint32_t sb = smem_u32(smem);
    const int t = threadIdx.x, lane = t & 31, wid = t >> 5;
    const int wm = wid % WARPS_M, wn = wid / WARPS_M;
    const int m0 = blockIdx.y * BM, n0 = blockIdx.x * 128;

    float c[2][NB][4];
#pragma unroll
    for (int s = 0; s < 2; s++)
#pragma unroll
        for (int nb = 0; nb < NB; nb++)
#pragma unroll
            for (int k = 0; k < 4; k++) c[s][nb][k] = 0.f;

    auto load_stage = [&](int st, int k0) {
        uint32_t sA = sb + st * STAGE;
        uint32_t sB = sA + ABYTES;
#pragma unroll
        for (int it = 0; it < BM * 8 / 256; it++) {
            int idx = t + it * 256;
            int r = idx >> 3, ch = idx & 7;
            const __nv_bfloat16* src = (ch < 4 ? Ah : Al)
                + (size_t)(m0 + r) * lda + k0 + (ch & 3) * 8;
            cpasync16(sA + r * 128 + ((ch ^ (r & 7)) * 16), src);
        }
#pragma unroll
        for (int it = 0; it < 4; it++) {
            int idx = t + it * 256;
            int p = idx >> 9, rem = idx & 511;
            int k = rem >> 4, ch = rem & 15;
            const __nv_bfloat16* src = (p ? Bl : Bh)
                + (size_t)(k0 + k) * ldb + n0 + ch * 8;
            cpasync16(sB + p * 8192 + k * 256 + ((ch ^ (k & 7)) * 16), src);
        }
    };

    const int klb = ((lane >> 3) & 1) * 8 + (lane & 7);
    const int nchb = wn * (WNT / 8) + (lane >> 4);

    const int NC = K / 32;
#pragma unroll
    for (int s = 0; s < NS - 1; s++) {
        if (s < NC) load_stage(s, s * 32);
        CP_COMMIT();
    }
    for (int cc = 0; cc < NC; cc++) {
        cp_wait<NS - 2>();
        __syncthreads();
        int nxt = cc + NS - 1;
        if (nxt < NC) load_stage(nxt % NS, nxt * 32);
        CP_COMMIT();

        uint32_t sA = sb + (cc % NS) * STAGE;
        uint32_t sB = sA + ABYTES;
#pragma unroll
        for (int c16 = 0; c16 < 2; c16++) {
            uint32_t ah[2][4], al[2][4];
#pragma unroll
            for (int s = 0; s < 2; s++) {
                int r = wm * 32 + s * 16 + (lane & 15);
                int lc = c16 * 2 + (lane >> 4);
                ldsm4(ah[s], sA + r * 128 + ((lc ^ (r & 7)) * 16));
                ldsm4(al[s], sA + r * 128 + (((lc + 4) ^ (r & 7)) * 16));
            }
#pragma unroll
            for (int g = 0; g < NG; g++) {
                int k = c16 * 16 + klb;
                int nch = nchb + g * 2;
                uint32_t boff = sB + k * 256 + ((nch ^ (k & 7)) * 16);
                uint32_t bh[4], bl[4];
                ldsm4t(bh, boff);
                ldsm4t(bl, boff + 8192);
#pragma unroll
                for (int s = 0; s < 2; s++) {
                    mma_bf16(c[s][2 * g],     ah[s], bh[0], bh[1]);
                    mma_bf16(c[s][2 * g + 1], ah[s], bh[2], bh[3]);
                    mma_bf16(c[s][2 * g],     ah[s], bl[0], bl[1]);
                    mma_bf16(c[s][2 * g + 1], ah[s], bl[2], bl[3]);
                    mma_bf16(c[s][2 * g],     al[s], bh[0], bh[1]);
                    mma_bf16(c[s][2 * g + 1], al[s], bh[2], bh[3]);
                }
            }
        }
    }

    const int gi = lane >> 2, ti = lane & 3;
#pragma unroll
    for (int s = 0; s < 2; s++) {
        int row = m0 + wm * 32 + s * 16 + gi;
#pragma unroll
        for (int nb = 0; nb < NB; nb++) {
            int col = n0 + wn * WNT + nb * 8 + ti * 2;
#pragma unroll
            for (int half = 0; half < 2; half++) {
                int rr = row + half * 8;
                float v0 = c[s][nb][half * 2], v1 = c[s][nb][half * 2 + 1];
                if (EPI == 0) {
                    __nv_bfloat16 h0, l0, h1, l1;
                    splitf(v0, h0, l0); splitf(v1, h1, l1);
                    uint32_t hv = (uint32_t)__bfloat16_as_ushort(h0)
                                | ((uint32_t)__bfloat16_as_ushort(h1) << 16);
                    uint32_t lv = (uint32_t)__bfloat16_as_ushort(l0)
                                | ((uint32_t)__bfloat16_as_ushort(l1) << 16);
                    *(uint32_t*)((__nv_bfloat16*)C0 + (size_t)rr * XP + col) = hv;
                    *(uint32_t*)((__nv_bfloat16*)C1 + (size_t)rr * XP + col) = lv;
                } else {
                    *(float2*)((float*)C0 + (size_t)rr * XP + col) =
                        make_float2(sigf(v0), sigf(v1));
                }
            }
        }
    }
}

// ---------------------------------------------------------------------------
// spmm prelude -> swizzled bf16 hi/lo smem planes [80 f-rows x 128B], pads zeroed
// ---------------------------------------------------------------------------
__device__ __forceinline__ void spmm_bf16_smem(int n, uint32_t XSH, uint32_t XSL,
    const __half* x0f, const unsigned short* sc, const float* sw, int nnz, int t)
{
    const float* xrow = g_x1 + (size_t)n * XP;
    for (int ch = t; ch < 640; ch += 256) {
        const int f = ch >> 3, bc = ch & 7;
        const uint32_t sw16 = ((uint32_t)(bc ^ (f & 7))) * 16;
        if (ch < 520) {
            const int jf = ch * 8;
            float acc[8];
#pragma unroll
            for (int q = 0; q < 8; q++) acc[q] = 0.f;
            int e = 0;
            for (; e + 1 < nnz; e += 2) {
                uint4 a = *(const uint4*)(x0f + (size_t)sc[e] * XP + jf);
                uint4 b = *(const uint4*)(x0f + (size_t)sc[e + 1] * XP + jf);
                float w0 = sw[e], w1 = sw[e + 1];
                const uint32_t* ua = &a.x;
                const uint32_t* ub = &b.x;
#pragma unroll
                for (int q = 0; q < 4; q++) {
                    float2 fa = __half22float2(*(const __half2*)&ua[q]);
                    float2 fb = __half22float2(*(const __half2*)&ub[q]);
                    acc[2 * q]     += w0 * fa.x + w1 * fb.x;
                    acc[2 * q + 1] += w0 * fa.y + w1 * fb.y;
                }
            }
            if (e < nnz) {
                uint4 a = *(const uint4*)(x0f + (size_t)sc[e] * XP + jf);
                float w0 = sw[e];
                const uint32_t* ua = &a.x;
#pragma unroll
                for (int q = 0; q < 4; q++) {
                    float2 fa = __half22float2(*(const __half2*)&ua[q]);
                    acc[2 * q]     += w0 * fa.x;
                    acc[2 * q + 1] += w0 * fa.y;
                }
            }
            float4 g0 = *(const float4*)(xrow + jf);
            float4 g1 = *(const float4*)(xrow + jf + 4);
            acc[0] += g0.x; acc[1] += g0.y; acc[2] += g0.z; acc[3] += g0.w;
            acc[4] += g1.x; acc[5] += g1.y; acc[6] += g1.z; acc[7] += g1.w;
            uint4 hv, lv;
            uint32_t* hw = &hv.x;
            uint32_t* lw = &lv.x;
#pragma unroll
            for (int q = 0; q < 4; q++) {
                __nv_bfloat16 h0, l0, h1, l1;
                splitf(acc[2 * q], h0, l0);
                splitf(acc[2 * q + 1], h1, l1);
                hw[q] = (uint32_t)__bfloat16_as_ushort(h0)
                      | ((uint32_t)__bfloat16_as_ushort(h1) << 16);
                lw[q] = (uint32_t)__bfloat16_as_ushort(l0)
                      | ((uint32_t)__bfloat16_as_ushort(l1) << 16);
            }
            sts128u(XSH + f * 128 + sw16, hv);
            sts128u(XSL + f * 128 + sw16, lv);
        } else {
            uint4 z = make_uint4(0, 0, 0, 0);
            sts128u(XSH + f * 128 + sw16, z);
            sts128u(XSL + f * 128 + sw16, z);
        }
    }
}

// node mma: D[j][b] = sum_f Wt[j][f] * xs[f][b];  Wt rows 160B (KP=80)
template<int JD, int NBB>
__device__ __forceinline__ void node_mma(uint32_t WTH, uint32_t WTL,
    uint32_t XSH, uint32_t XSL, int lane, int wm, int wn, float c[2][NBB][4])
{
    constexpr int NGB = NBB / 2;
    const int klb = ((lane >> 3) & 1) * 8 + (lane & 7);
    const int nchb = wn * NBB + (lane >> 4);
#pragma unroll
    for (int k16 = 0; k16 < 5; k16++) {
        uint32_t ah[2][4], al[2][4];
#pragma unroll
        for (int s = 0; s < 2; s++) {
            int r = wm * 32 + s * 16 + (lane & 15);
            int lc = k16 * 2 + (lane >> 4);
            ldsm4(ah[s], WTH + r * 160 + lc * 16);
            ldsm4(al[s], WTL + r * 160 + lc * 16);
        }
#pragma unroll
        for (int g = 0; g < NGB; g++) {
            int k = k16 * 16 + klb;
            int nch = nchb + g * 2;
            uint32_t boff = k * 128 + ((uint32_t)(nch ^ (k & 7))) * 16;
            uint32_t bh[4], bl[4];
            ldsm4t(bh, XSH + boff);
            ldsm4t(bl, XSL + boff);
#pragma unroll
            for (int s = 0; s < 2; s++) {
                mma_bf16(c[s][2 * g],     ah[s], bh[0], bh[1]);
                mma_bf16(c[s][2 * g + 1], ah[s], bh[2], bh[3]);
                mma_bf16(c[s][2 * g],     ah[s], bl[0], bl[1]);
                mma_bf16(c[s][2 * g + 1], ah[s], bl[2], bl[3]);
                mma_bf16(c[s][2 * g],     al[s], bh[0], bh[1]);
                mma_bf16(c[s][2 * g + 1], al[s], bh[2], bh[3]);
            }
        }
    }
}

// ---------------------------------------------------------------------------
// gate: smem 78848 B. xs [0,20480), Wt [20480,61440), st [61440,78080),
// sc [78080,78336), sw [78336,78848)
// ---------------------------------------------------------------------------
__global__ __launch_bounds__(256, 2)
void gate_kernel(const float* __restrict__ inputs, const float* __restrict__ state,
                 const float* __restrict__ b0)
{
    extern __shared__ char smem[];
    const uint32_t sb = smem_u32(smem);
    const uint32_t XSH = sb, XSL = sb + 10240;
    const uint32_t WTH = sb + 20480, WTL = WTH + 128 * 160;
    float* st = (float*)(smem + 61440);
    unsigned short* sc = (unsigned short*)(smem + 78080);
    float* sw = (float*)(smem + 78336);

    const int n = blockIdx.x, t = threadIdx.x;
    const int lane = t & 31, wid = t >> 5;
    const int wm = wid & 3, wn = wid >> 2;   // WM=4, WN=2

    if (t < ELLW) {
        sc[t] = g_cols[(size_t)n * ELLW + t];
        sw[t] = g_wts[(size_t)n * ELLW + t];
    }
    // copy Wt planes: 128*160/16 = 1280 chunks per plane
    for (int idx = t; idx < 2560; idx += 256) {
        int p = idx >= 1280;
        int i = idx - p * 1280;
        const uint4* src = (const uint4*)(p ? (const void*)g_wt0l : (const void*)g_wt0h) + i;
        sts128u((p ? WTL : WTH) + i * 16, __ldg(src));
    }
    __syncthreads();
    const int nnz = g_nnz[n];
    spmm_bf16_smem(n, XSH, XSL, g_x0fA, sc, sw, nnz, t);
    __syncthreads();

    float c[2][4][4];
#pragma unroll
    for (int s = 0; s < 2; s++)
#pragma unroll
        for (int nb = 0; nb < 4; nb++)
#pragma unroll
            for (int e = 0; e < 4; e++) c[s][nb][e] = 0.f;
    node_mma<128, 4>(WTH, WTL, XSH, XSL, lane, wm, wn, c);

    const int gi = lane >> 2, ti = lane & 3;
    __nv_bfloat16* rh = g_x0h + (size_t)n * XP;
    __nv_bfloat16* rl = g_x0l + (size_t)n * XP;
    __half*        rf = g_x0fB + (size_t)n * XP;

    // phase 1: r (j < 64) -> st[b*65+j] = sig * state
    if (wm < 2) {
#pragma unroll
        for (int s = 0; s < 2; s++)
#pragma unroll
            for (int nb = 0; nb < 4; nb++)
#pragma unroll
                for (int e = 0; e < 4; e++) {
                    int j = wm * 32 + s * 16 + gi + ((e >= 2) ? 8 : 0);
                    int b = wn * 32 + nb * 8 + ti * 2 + (e & 1);
                    float r = sigf(c[s][nb][e] + __ldg(b0 + j));
                    st[b * 65 + j] = r * __ldg(state + (size_t)b * SSTRIDE + n * 64 + j);
                }
    }
    __syncthreads();
    for (int i = t; i < 4096; i += 256) {
        int j = i >> 6, b = i & 63;
        float v = st[b * 65 + j];
        __nv_bfloat16 h, l; splitf(v, h, l);
        rh[64 + i] = h; rl[64 + i] = l; rf[64 + i] = __float2half(v);
    }
    if (t < 64) {
        float v = inputs[t * NN + n];
        __nv_bfloat16 h, l; splitf(v, h, l);
        rh[t] = h; rl[t] = l; rf[t] = __float2half(v);
    }
    __syncthreads();
    // phase 2: u (j >= 64)
    if (wm >= 2) {
#pragma unroll
        for (int s = 0; s < 2; s++)
#pragma unroll
            for (int nb = 0; nb < 4; nb++)
#pragma unroll
                for (int e = 0; e < 4; e++) {
                    int j = wm * 32 + s * 16 + gi + ((e >= 2) ? 8 : 0);
                    int b = wn * 32 + nb * 8 + ti * 2 + (e & 1);
                    st[b * 65 + (j - 64)] = sigf(c[s][nb][e] + __ldg(b0 + j));
                }
    }
    __syncthreads();
    for (int i = t; i < 4096; i += 256) {
        int b = i >> 6, ju = i & 63;
        g_u[(size_t)b * SSTRIDE + n * 64 + ju] = st[b * 65 + ju];
    }
}

// ---------------------------------------------------------------------------
// cand: smem 58368 B. xs [0,20480), Wt [20480,40960), st [40960,57600),
// sc [57600,57856), sw [57856,58368)
// ---------------------------------------------------------------------------
__global__ __launch_bounds__(256, 2)
void cand_kernel(const float* __restrict__ state, const float* __restrict__ b1,
                 float* __restrict__ out)
{
    extern __shared__ char smem[];
    const uint32_t sb = smem_u32(smem);
    const uint32_t XSH = sb, XSL = sb + 10240;
    const uint32_t WTH = sb + 20480, WTL = WTH + 64 * 160;
    float* st = (float*)(smem + 40960);
    unsigned short* sc = (unsigned short*)(smem + 57600);
    float* sw = (float*)(smem + 57856);

    const int n = blockIdx.x, t = threadIdx.x;
    const int lane = t & 31, wid = t >> 5;
    const int wm = wid & 1, wn = wid >> 1;   // WM=2, WN=4

    if (t < ELLW) {
        sc[t] = g_cols[(size_t)n * ELLW + t];
        sw[t] = g_wts[(size_t)n * ELLW + t];
    }
    // copy Wt planes: 64*160/16 = 640 chunks per plane
    for (int idx = t; idx < 1280; idx += 256) {
        int p = idx >= 640;
        int i = idx - p * 640;
        const uint4* src = (const uint4*)(p ? (const void*)g_wt1l : (const void*)g_wt1h) + i;
        sts128u((p ? WTL : WTH) + i * 16, __ldg(src));
    }
    __syncthreads();
    const int nnz = g_nnz[n];
    spmm_bf16_smem(n, XSH, XSL, g_x0fB, sc, sw, nnz, t);
    __syncthreads();

    float c[2][2][4];
#pragma unroll
    for (int s = 0; s < 2; s++)
#pragma unroll
        for (int nb = 0; nb < 2; nb++)
#pragma unroll
            for (int e = 0; e < 4; e++) c[s][nb][e] = 0.f;
    node_mma<64, 2>(WTH, WTL, XSH, XSL, lane, wm, wn, c);

    const int gi = lane >> 2, ti = lane & 3;
#pragma unroll
    for (int s = 0; s < 2; s++)
#pragma unroll
        for (int nb = 0; nb < 2; nb++)
#pragma unroll
            for (int e = 0; e < 4; e++) {
                int j = wm * 32 + s * 16 + gi + ((e >= 2) ? 8 : 0);
                int b = wn * 16 + nb * 8 + ti * 2 + (e & 1);
                st[b * 65 + j] = tanhf(c[s][nb][e] + __ldg(b1 + j));
            }
    __syncthreads();
    for (int i = t; i < 4096; i += 256) {
        int b = i >> 6, j = i & 63;
        size_t addr = (size_t)b * SSTRIDE + n * 64 + j;
        float u = g_u[addr], s = state[addr];
        out[addr] = u * s + (1.f - u) * st[b * 65 + j];
    }
}

// ---------------------------------------------------------------------------
extern "C" void kernel_launch(void* const* d_in, const int* in_sizes, int n_in,
                              void* d_out, int out_size)
{
    const float* inputs = (const float*)d_in[0];
    const float* state  = (const float*)d_in[1];
    const float* adj    = (const float*)d_in[2];
    const float* afc    = (const float*)d_in[4];
    const float* afct   = (const float*)d_in[5];
    const float* w0     = (const float*)d_in[6];
    const float* b0     = (const float*)d_in[7];
    const float* w1     = (const float*)d_in[8];
    const float* b1     = (const float*)d_in[9];
    float* out = (float*)d_out;

    __nv_bfloat16 *x0h, *x0l, *fch, *fcl, *afch, *afcl, *afcth, *afctl;
    float* x1;
    cudaGetSymbolAddress((void**)&x0h,   g_x0h);
    cudaGetSymbolAddress((void**)&x0l,   g_x0l);
    cudaGetSymbolAddress((void**)&fch,   g_fch);
    cudaGetSymbolAddress((void**)&fcl,   g_fcl);
    cudaGetSymbolAddress((void**)&afch,  g_afch);
    cudaGetSymbolAddress((void**)&afcl,  g_afcl);
    cudaGetSymbolAddress((void**)&afcth, g_afcth);
    cudaGetSymbolAddress((void**)&afctl, g_afctl);
    cudaGetSymbolAddress((void**)&x1,    g_x1);

    const int SM_FC   = 4 * (64 * 128 + 16384);    // 98304
    const int SM_BIG  = 3 * (128 * 128 + 16384);   // 98304
    const int SM_GATE = 78848;
    const int SM_CAND = 58368;
    cudaFuncSetAttribute(gemm_mma<64, 0, 4>,  cudaFuncAttributeMaxDynamicSharedMemorySize, SM_FC);
    cudaFuncSetAttribute(gemm_mma<128, 1, 3>, cudaFuncAttributeMaxDynamicSharedMemorySize, SM_BIG);
    cudaFuncSetAttribute(gate_kernel, cudaFuncAttributeMaxDynamicSharedMemorySize, SM_GATE);
    cudaFuncSetAttribute(cand_kernel, cudaFuncAttributeMaxDynamicSharedMemorySize, SM_CAND);

    dim3 blk(256);
    setup_kernel<<<NN, blk>>>(adj, afc, afct, inputs, state, w0, w1);

    for (int pass = 0; pass < 2; pass++) {
        gemm_mma<64, 0, 4><<<dim3(XP / 128, CN / 64), blk, SM_FC>>>(
            afch, afcl, x0h, x0l, fch, fcl, NN, NN, XP);
        gemm_mma<128, 1, 3><<<dim3(XP / 128, NN / 128), blk, SM_BIG>>>(
            afcth, afctl, fch, fcl, x1, nullptr, CN, CN, XP);
        if (pass == 0)
            gate_kernel<<<NN, blk, SM_GATE>>>(inputs, state, b0);
        else
            cand_kernel<<<NN, blk, SM_CAND>>>(state, b1, out);
    }
}

// round 15
// speedup vs baseline: 1.1222x; 1.1222x over previous
#include <cuda_runtime.h>
#include <cuda_bf16.h>
#include <cuda_fp16.h>
#include <math.h>
#include <cstdint>
#include <cstddef>

#define NN 2048
#define CN 256
#define XP 4224          // padded column stride (33*128)
#define FBC 4160         // real columns = 65*64
#define SSTRIDE 131072   // NN*64
#define ELLW 128

// ---------------- scratch (device globals) ---------------------------------
__device__ __nv_bfloat16 g_x0h[(size_t)NN * XP];
__device__ __nv_bfloat16 g_x0l[(size_t)NN * XP];
__device__ __half        g_x0fA[(size_t)NN * XP];
__device__ __half        g_x0fB[(size_t)NN * XP];
__device__ __nv_bfloat16 g_fch[(size_t)CN * XP];
__device__ __nv_bfloat16 g_fcl[(size_t)CN * XP];
__device__ __nv_bfloat16 g_afch[(size_t)CN * NN];
__device__ __nv_bfloat16 g_afcl[(size_t)CN * NN];
__device__ __nv_bfloat16 g_afcth[(size_t)NN * CN];
__device__ __nv_bfloat16 g_afctl[(size_t)NN * CN];
__device__ float    g_x1[(size_t)NN * XP];
__device__ float    g_u[(size_t)64 * SSTRIDE];
__device__ unsigned short g_cols[(size_t)NN * ELLW];
__device__ float    g_wts[(size_t)NN * ELLW];
__device__ int      g_nnz[NN];

__device__ __forceinline__ float sigf(float x) { return 1.0f / (1.0f + expf(-x)); }
__device__ __forceinline__ void splitf(float v, __nv_bfloat16& h, __nv_bfloat16& l) {
    h = __float2bfloat16(v);
    l = __float2bfloat16(v - __bfloat162float(h));
}
__device__ __forceinline__ uint32_t smem_u32(const void* p) {
    uint32_t a;
    asm("{ .reg .u64 t; cvta.to.shared.u64 t, %1; cvt.u32.u64 %0, t; }" : "=r"(a) : "l"(p));
    return a;
}
__device__ __forceinline__ void cpasync16(uint32_t s, const void* g) {
    asm volatile("cp.async.cg.shared.global [%0], [%1], 16;" :: "r"(s), "l"(g));
}
#define CP_COMMIT() asm volatile("cp.async.commit_group;" ::: "memory")
template<int N> __device__ __forceinline__ void cp_wait() {
    asm volatile("cp.async.wait_group %0;" :: "n"(N) : "memory");
}

__device__ __forceinline__ void ldsm4(uint32_t* r, uint32_t a) {
    asm volatile("ldmatrix.sync.aligned.m8n8.x4.shared.b16 {%0,%1,%2,%3}, [%4];"
        : "=r"(r[0]), "=r"(r[1]), "=r"(r[2]), "=r"(r[3]) : "r"(a));
}
__device__ __forceinline__ void ldsm4t(uint32_t* r, uint32_t a) {
    asm volatile("ldmatrix.sync.aligned.m8n8.x4.trans.shared.b16 {%0,%1,%2,%3}, [%4];"
        : "=r"(r[0]), "=r"(r[1]), "=r"(r[2]), "=r"(r[3]) : "r"(a));
}
__device__ __forceinline__ void mma_bf16(float* c, const uint32_t* a, uint32_t b0, uint32_t b1) {
    asm volatile("mma.sync.aligned.m16n8k16.row.col.f32.bf16.bf16.f32 "
        "{%0,%1,%2,%3}, {%4,%5,%6,%7}, {%8,%9}, {%0,%1,%2,%3};"
        : "+f"(c[0]), "+f"(c[1]), "+f"(c[2]), "+f"(c[3])
        : "r"(a[0]), "r"(a[1]), "r"(a[2]), "r"(a[3]), "r"(b0), "r"(b1));
}

// ---------------------------------------------------------------------------
// setup: ELL compaction (block scan) + weight convert + pack x0
// ---------------------------------------------------------------------------
__global__ __launch_bounds__(256) void setup_kernel(const float* __restrict__ adj,
    const float* __restrict__ afc, const float* __restrict__ afct,
    const float* __restrict__ inputs, const float* __restrict__ state)
{
    __shared__ float tile[64 * 65];
    __shared__ int wsum[8];
    const int n = blockIdx.x, t = threadIdx.x;
    const int lane = t & 31, wid = t >> 5;

    {
        int i = n * 256 + t;
        __nv_bfloat16 h, l;
        splitf(afc[i],  h, l); g_afch[i]  = h; g_afcl[i]  = l;
        splitf(afct[i], h, l); g_afcth[i] = h; g_afctl[i] = l;
    }

    const float* row = adj + (size_t)n * NN;
    float v[8];
    float4 p0 = *(const float4*)(row + t * 8);
    float4 p1 = *(const float4*)(row + t * 8 + 4);
    v[0] = p0.x; v[1] = p0.y; v[2] = p0.z; v[3] = p0.w;
    v[4] = p1.x; v[5] = p1.y; v[6] = p1.z; v[7] = p1.w;
    int cnt = 0;
#pragma unroll
    for (int q = 0; q < 8; q++) cnt += (v[q] != 0.0f);
    int inc = cnt;
#pragma unroll
    for (int off = 1; off < 32; off <<= 1) {
        int y = __shfl_up_sync(0xFFFFFFFFu, inc, off);
        if (lane >= off) inc += y;
    }
    if (lane == 31) wsum[wid] = inc;
    __syncthreads();
    int wbase = 0;
#pragma unroll
    for (int w = 0; w < 8; w++) wbase += (w < wid) ? wsum[w] : 0;
    int pos = wbase + inc - cnt;
#pragma unroll
    for (int q = 0; q < 8; q++) {
        if (v[q] != 0.0f) {
            if (pos < ELLW) {
                g_cols[(size_t)n * ELLW + pos] = (unsigned short)(t * 8 + q);
                g_wts[(size_t)n * ELLW + pos] = v[q];
            }
            pos++;
        }
    }
    if (t == 255) g_nnz[n] = (pos < ELLW) ? pos : ELLW;

    for (int i = t; i < 4096; i += 256) {
        int b = i >> 6, u = i & 63;
        tile[b * 65 + u] = state[(size_t)b * SSTRIDE + n * 64 + u];
    }
    __syncthreads();
    __nv_bfloat16* rh = g_x0h + (size_t)n * XP;
    __nv_bfloat16* rl = g_x0l + (size_t)n * XP;
    __half*        rf = g_x0fA + (size_t)n * XP;
    if (t < 64) {
        float vv = inputs[t * NN + n];
        __nv_bfloat16 h, l; splitf(vv, h, l);
        rh[t] = h; rl[t] = l; rf[t] = __float2half(vv);
    }
    for (int i = t; i < 4096; i += 256) {
        int u = i >> 6, b = i & 63;
        float vv = tile[b * 65 + u];
        __nv_bfloat16 h, l; splitf(vv, h, l);
        rh[64 + i] = h; rl[64 + i] = l; rf[64 + i] = __float2half(vv);
    }
}

// ---------------------------------------------------------------------------
// dense gemm (R10 config): C(Mx4224) = A(MxK) @ B(Kx4224), split-3 bf16
// ---------------------------------------------------------------------------
template<int BM, int EPI, int NS>
__global__ __launch_bounds__(256, 2) void gemm_mma(
    const __nv_bfloat16* __restrict__ Ah, const __nv_bfloat16* __restrict__ Al,
    const __nv_bfloat16* __restrict__ Bh, const __nv_bfloat16* __restrict__ Bl,
    void* __restrict__ C0, void* __restrict__ C1, int K, int lda, int ldb)
{
    extern __shared__ char smem[];
    constexpr int ABYTES = BM * 128;
    constexpr int STAGE  = ABYTES + 16384;
    constexpr int WARPS_M = BM / 32;
    constexpr int WNT = 128 / (8 / WARPS_M);
    constexpr int NB = WNT / 8, NG = WNT / 16;

    const uint32_t sb = smem_u32(smem);
    const int t = threadIdx.x, lane = t & 31, wid = t >> 5;
    const int wm = wid % WARPS_M, wn = wid / WARPS_M;
    const int m0 = blockIdx.y * BM, n0 = blockIdx.x * 128;

    float c[2][NB][4];
#pragma unroll
    for (int s = 0; s < 2; s++)
#pragma unroll
        for (int nb = 0; nb < NB; nb++)
#pragma unroll
            for (int k = 0; k < 4; k++) c[s][nb][k] = 0.f;

    auto load_stage = [&](int st, int k0) {
        uint32_t sA = sb + st * STAGE;
        uint32_t sB = sA + ABYTES;
#pragma unroll
        for (int it = 0; it < BM * 8 / 256; it++) {
            int idx = t + it * 256;
            int r = idx >> 3, ch = idx & 7;
            const __nv_bfloat16* src = (ch < 4 ? Ah : Al)
                + (size_t)(m0 + r) * lda + k0 + (ch & 3) * 8;
            cpasync16(sA + r * 128 + ((ch ^ (r & 7)) * 16), src);
        }
#pragma unroll
        for (int it = 0; it < 4; it++) {
            int idx = t + it * 256;
            int p = idx >> 9, rem = idx & 511;
            int k = rem >> 4, ch = rem & 15;
            const __nv_bfloat16* src = (p ? Bl : Bh)
                + (size_t)(k0 + k) * ldb + n0 + ch * 8;
            cpasync16(sB + p * 8192 + k * 256 + ((ch ^ (k & 7)) * 16), src);
        }
    };

    const int klb = ((lane >> 3) & 1) * 8 + (lane & 7);
    const int nchb = wn * (WNT / 8) + (lane >> 4);

    const int NC = K / 32;
#pragma unroll
    for (int s = 0; s < NS - 1; s++) {
        if (s < NC) load_stage(s, s * 32);
        CP_COMMIT();
    }
    for (int cc = 0; cc < NC; cc++) {
        cp_wait<NS - 2>();
        __syncthreads();
        int nxt = cc + NS - 1;
        if (nxt < NC) load_stage(nxt % NS, nxt * 32);
        CP_COMMIT();

        uint32_t sA = sb + (cc % NS) * STAGE;
        uint32_t sB = sA + ABYTES;
#pragma unroll
        for (int c16 = 0; c16 < 2; c16++) {
            uint32_t ah[2][4], al[2][4];
#pragma unroll
            for (int s = 0; s < 2; s++) {
                int r = wm * 32 + s * 16 + (lane & 15);
                int lc = c16 * 2 + (lane >> 4);
                ldsm4(ah[s], sA + r * 128 + ((lc ^ (r & 7)) * 16));
                ldsm4(al[s], sA + r * 128 + (((lc + 4) ^ (r & 7)) * 16));
            }
#pragma unroll
            for (int g = 0; g < NG; g++) {
                int k = c16 * 16 + klb;
                int nch = nchb + g * 2;
                uint32_t boff = sB + k * 256 + ((nch ^ (k & 7)) * 16);
                uint32_t bh[4], bl[4];
                ldsm4t(bh, boff);
                ldsm4t(bl, boff + 8192);
#pragma unroll
                for (int s = 0; s < 2; s++) {
                    mma_bf16(c[s][2 * g],     ah[s], bh[0], bh[1]);
                    mma_bf16(c[s][2 * g + 1], ah[s], bh[2], bh[3]);
                    mma_bf16(c[s][2 * g],     ah[s], bl[0], bl[1]);
                    mma_bf16(c[s][2 * g + 1], ah[s], bl[2], bl[3]);
                    mma_bf16(c[s][2 * g],     al[s], bh[0], bh[1]);
                    mma_bf16(c[s][2 * g + 1], al[s], bh[2], bh[3]);
                }
            }
        }
    }

    const int gi = lane >> 2, ti = lane & 3;
#pragma unroll
    for (int s = 0; s < 2; s++) {
        int row = m0 + wm * 32 + s * 16 + gi;
#pragma unroll
        for (int nb = 0; nb < NB; nb++) {
            int col = n0 + wn * WNT + nb * 8 + ti * 2;
#pragma unroll
            for (int half = 0; half < 2; half++) {
                int rr = row + half * 8;
                float v0 = c[s][nb][half * 2], v1 = c[s][nb][half * 2 + 1];
                if (EPI == 0) {
                    __nv_bfloat16 h0, l0, h1, l1;
                    splitf(v0, h0, l0); splitf(v1, h1, l1);
                    uint32_t hv = (uint32_t)__bfloat16_as_ushort(h0)
                                | ((uint32_t)__bfloat16_as_ushort(h1) << 16);
                    uint32_t lv = (uint32_t)__bfloat16_as_ushort(l0)
                                | ((uint32_t)__bfloat16_as_ushort(l1) << 16);
                    *(uint32_t*)((__nv_bfloat16*)C0 + (size_t)rr * XP + col) = hv;
                    *(uint32_t*)((__nv_bfloat16*)C1 + (size_t)rr * XP + col) = lv;
                } else {
                    *(float2*)((float*)C0 + (size_t)rr * XP + col) =
                        make_float2(sigf(v0), sigf(v1));
                }
            }
        }
    }
}

// ---------------------------------------------------------------------------
// spmm prelude: xs[0..FBC) = x1[n,:] + sum_e w * x0f_src[cols[e], :]
// ---------------------------------------------------------------------------
__device__ __forceinline__ void spmm_into_smem(int n, float* xs, const __half* x0f,
    const unsigned short* sc, const float* sw, int nnz, int t)
{
    const float* xrow = g_x1 + (size_t)n * XP;
#pragma unroll
    for (int sub = 0; sub < 3; sub++) {
        int ch = sub * 256 + t;
        if (ch < 520) {
            const int jf = ch * 8;
            float acc[8];
#pragma unroll
            for (int q = 0; q < 8; q++) acc[q] = 0.f;
            int e = 0;
            for (; e + 1 < nnz; e += 2) {
                uint4 a = *(const uint4*)(x0f + (size_t)sc[e] * XP + jf);
                uint4 b = *(const uint4*)(x0f + (size_t)sc[e + 1] * XP + jf);
                float w0 = sw[e], w1 = sw[e + 1];
                const uint32_t* ua = &a.x;
                const uint32_t* ub = &b.x;
#pragma unroll
                for (int q = 0; q < 4; q++) {
                    float2 fa = __half22float2(*(const __half2*)&ua[q]);
                    float2 fb = __half22float2(*(const __half2*)&ub[q]);
                    acc[2 * q]     += w0 * fa.x + w1 * fb.x;
                    acc[2 * q + 1] += w0 * fa.y + w1 * fb.y;
                }
            }
            if (e < nnz) {
                uint4 a = *(const uint4*)(x0f + (size_t)sc[e] * XP + jf);
                float w0 = sw[e];
                const uint32_t* ua = &a.x;
#pragma unroll
                for (int q = 0; q < 4; q++) {
                    float2 fa = __half22float2(*(const __half2*)&ua[q]);
                    acc[2 * q]     += w0 * fa.x;
                    acc[2 * q + 1] += w0 * fa.y;
                }
            }
            float4 g0 = *(const float4*)(xrow + jf);
            float4 g1 = *(const float4*)(xrow + jf + 4);
            xs[jf + 0] = g0.x + acc[0]; xs[jf + 1] = g0.y + acc[1];
            xs[jf + 2] = g0.z + acc[2]; xs[jf + 3] = g0.w + acc[3];
            xs[jf + 4] = g1.x + acc[4]; xs[jf + 5] = g1.y + acc[5];
            xs[jf + 6] = g1.z + acc[6]; xs[jf + 7] = g1.w + acc[7];
        }
    }
}

// ---------------------------------------------------------------------------
// gate (fused spmm, plane A -> plane B): W0 staged in smem (LDS, not LDG)
// dyn smem: xs [0,16640) st [16640,33280) ws [33280,66560) sc [66560,66816)
//           sw [66816,67328)
// ---------------------------------------------------------------------------
__global__ __launch_bounds__(256)
void gate_kernel(const float* __restrict__ inputs, const float* __restrict__ state,
                 const float* __restrict__ w0, const float* __restrict__ b0)
{
    extern __shared__ char smem[];
    float* xs = (float*)smem;
    float* st = (float*)(smem + 16640);
    float* ws = (float*)(smem + 33280);
    unsigned short* sc = (unsigned short*)(smem + 66560);
    float* sw = (float*)(smem + 66816);

    const int n = blockIdx.x, t = threadIdx.x;
    if (t < ELLW) {
        sc[t] = g_cols[(size_t)n * ELLW + t];
        sw[t] = g_wts[(size_t)n * ELLW + t];
    }
    // stage W0 (65x128 fp32 = 2080 uint4)
    for (int i = t; i < 2080; i += 256)
        *((uint4*)ws + i) = __ldg((const uint4*)w0 + i);
    __syncthreads();
    const int nnz = g_nnz[n];
    spmm_into_smem(n, xs, g_x0fA, sc, sw, nnz, t);
    __syncthreads();

    const int jt = t & 15, bt = t >> 4;
    const int j0 = jt * 8, b0v = bt * 4;
    float acc[4][8];
#pragma unroll
    for (int i = 0; i < 4; i++)
#pragma unroll
        for (int k = 0; k < 8; k++) acc[i][k] = 0.f;

    for (int f = 0; f < 65; f++) {
        float xv[4];
#pragma unroll
        for (int i = 0; i < 4; i++) xv[i] = xs[f * 64 + b0v + i];
        float4 wa = *(const float4*)(ws + f * 128 + j0);
        float4 wb = *(const float4*)(ws + f * 128 + j0 + 4);
        float wv[8] = {wa.x, wa.y, wa.z, wa.w, wb.x, wb.y, wb.z, wb.w};
#pragma unroll
        for (int i = 0; i < 4; i++)
#pragma unroll
            for (int k = 0; k < 8; k++) acc[i][k] += xv[i] * wv[k];
    }
    float bb[8];
#pragma unroll
    for (int k = 0; k < 8; k++) bb[k] = __ldg(b0 + j0 + k);

    __nv_bfloat16* rh = g_x0h + (size_t)n * XP;
    __nv_bfloat16* rl = g_x0l + (size_t)n * XP;
    __half*        rf = g_x0fB + (size_t)n * XP;

    if (jt < 8) {
#pragma unroll
        for (int i = 0; i < 4; i++)
#pragma unroll
            for (int k = 0; k < 8; k++) {
                int j = j0 + k, b = b0v + i;
                float r = sigf(acc[i][k] + bb[k]);
                st[b * 65 + j] = r * __ldg(state + (size_t)b * SSTRIDE + n * 64 + j);
            }
    }
    __syncthreads();
    for (int i = t; i < 4096; i += 256) {
        int j = i >> 6, b = i & 63;
        float v = st[b * 65 + j];
        __nv_bfloat16 h, l; splitf(v, h, l);
        rh[64 + i] = h; rl[64 + i] = l; rf[64 + i] = __float2half(v);
    }
    if (t < 64) {
        float v = inputs[t * NN + n];
        __nv_bfloat16 h, l; splitf(v, h, l);
        rh[t] = h; rl[t] = l; rf[t] = __float2half(v);
    }
    __syncthreads();

    if (jt >= 8) {
#pragma unroll
        for (int i = 0; i < 4; i++)
#pragma unroll
            for (int k = 0; k < 8; k++) {
                int ju = j0 - 64 + k, b = b0v + i;
                st[b * 65 + ju] = sigf(acc[i][k] + bb[k]);
            }
    }
    __syncthreads();
    for (int i = t; i < 4096; i += 256) {
        int b = i >> 6, ju = i & 63;
        g_u[(size_t)b * SSTRIDE + n * 64 + ju] = st[b * 65 + ju];
    }
}

// ---------------------------------------------------------------------------
// cand (fused spmm, plane B): W1 staged in smem
// dyn smem: xs [0,16640) st [16640,33280) ws [33280,49920) sc [49920,50176)
//           sw [50176,50688)
// ---------------------------------------------------------------------------
__global__ __launch_bounds__(256)
void cand_kernel(const float* __restrict__ state, const float* __restrict__ w1,
                 const float* __restrict__ b1, float* __restrict__ out)
{
    extern __shared__ char smem[];
    float* xs = (float*)smem;
    float* st = (float*)(smem + 16640);
    float* ws = (float*)(smem + 33280);
    unsigned short* sc = (unsigned short*)(smem + 49920);
    float* sw = (float*)(smem + 50176);

    const int n = blockIdx.x, t = threadIdx.x;
    if (t < ELLW) {
        sc[t] = g_cols[(size_t)n * ELLW + t];
        sw[t] = g_wts[(size_t)n * ELLW + t];
    }
    // stage W1 (65x64 fp32 = 1040 uint4)
    for (int i = t; i < 1040; i += 256)
        *((uint4*)ws + i) = __ldg((const uint4*)w1 + i);
    __syncthreads();
    const int nnz = g_nnz[n];
    spmm_into_smem(n, xs, g_x0fB, sc, sw, nnz, t);
    __syncthreads();

    const int jt = t & 15, bt = t >> 4;
    const int j0 = jt * 4, b0v = bt * 4;
    float acc[4][4];
#pragma unroll
    for (int i = 0; i < 4; i++)
#pragma unroll
        for (int k = 0; k < 4; k++) acc[i][k] = 0.f;

    for (int f = 0; f < 65; f++) {
        float xv[4];
#pragma unroll
        for (int i = 0; i < 4; i++) xv[i] = xs[f * 64 + b0v + i];
        float4 w4 = *(const float4*)(ws + f * 64 + j0);
        float wv[4] = {w4.x, w4.y, w4.z, w4.w};
#pragma unroll
        for (int i = 0; i < 4; i++)
#pragma unroll
            for (int k = 0; k < 4; k++) acc[i][k] += xv[i] * wv[k];
    }
#pragma unroll
    for (int i = 0; i < 4; i++)
#pragma unroll
        for (int k = 0; k < 4; k++) {
            int j = j0 + k, b = b0v + i;
            st[b * 65 + j] = tanhf(acc[i][k] + __ldg(b1 + j));
        }
    __syncthreads();
    for (int i = t; i < 4096; i += 256) {
        int b = i >> 6, j = i & 63;
        size_t addr = (size_t)b * SSTRIDE + n * 64 + j;
        float u = g_u[addr], s = state[addr];
        out[addr] = u * s + (1.f - u) * st[b * 65 + j];
    }
}

// ---------------------------------------------------------------------------
extern "C" void kernel_launch(void* const* d_in, const int* in_sizes, int n_in,
                              void* d_out, int out_size)
{
    const float* inputs = (const float*)d_in[0];
    const float* state  = (const float*)d_in[1];
    const float* adj    = (const float*)d_in[2];
    const float* afc    = (const float*)d_in[4];
    const float* afct   = (const float*)d_in[5];
    const float* w0     = (const float*)d_in[6];
    const float* b0     = (const float*)d_in[7];
    const float* w1     = (const float*)d_in[8];
    const float* b1     = (const float*)d_in[9];
    float* out = (float*)d_out;

    __nv_bfloat16 *x0h, *x0l, *fch, *fcl, *afch, *afcl, *afcth, *afctl;
    float* x1;
    cudaGetSymbolAddress((void**)&x0h,   g_x0h);
    cudaGetSymbolAddress((void**)&x0l,   g_x0l);
    cudaGetSymbolAddress((void**)&fch,   g_fch);
    cudaGetSymbolAddress((void**)&fcl,   g_fcl);
    cudaGetSymbolAddress((void**)&afch,  g_afch);
    cudaGetSymbolAddress((void**)&afcl,  g_afcl);
    cudaGetSymbolAddress((void**)&afcth, g_afcth);
    cudaGetSymbolAddress((void**)&afctl, g_afctl);
    cudaGetSymbolAddress((void**)&x1,    g_x1);

    const int SM_FC   = 4 * (64 * 128 + 16384);    // 98304
    const int SM_BIG  = 3 * (128 * 128 + 16384);   // 98304
    const int SM_GATE = 67328;
    const int SM_CAND = 50688;
    cudaFuncSetAttribute(gemm_mma<64, 0, 4>,  cudaFuncAttributeMaxDynamicSharedMemorySize, SM_FC);
    cudaFuncSetAttribute(gemm_mma<128, 1, 3>, cudaFuncAttributeMaxDynamicSharedMemorySize, SM_BIG);
    cudaFuncSetAttribute(gate_kernel, cudaFuncAttributeMaxDynamicSharedMemorySize, SM_GATE);
    cudaFuncSetAttribute(cand_kernel, cudaFuncAttributeMaxDynamicSharedMemorySize, SM_CAND);

    dim3 blk(256);
    setup_kernel<<<NN, blk>>>(adj, afc, afct, inputs, state);

    for (int pass = 0; pass < 2; pass++) {
        gemm_mma<64, 0, 4><<<dim3(XP / 128, CN / 64), blk, SM_FC>>>(
            afch, afcl, x0h, x0l, fch, fcl, NN, NN, XP);
        gemm_mma<128, 1, 3><<<dim3(XP / 128, NN / 128), blk, SM_BIG>>>(
            afcth, afctl, fch, fcl, x1, nullptr, CN, CN, XP);
        if (pass == 0)
            gate_kernel<<<NN, blk, SM_GATE>>>(inputs, state, w0, b0);
        else
            cand_kernel<<<NN, blk, SM_CAND>>>(state, w1, b1, out);
    }
}